// round 2
// baseline (speedup 1.0000x reference)
#include <cuda_runtime.h>

#define TD    512   // timesteps
#define BD    512   // batch
#define HID   32    // hidden
#define G4    128   // 4*HID gate rows
#define EMBD  32
#define VOCAB 1000
#define FF    16
#define NCLS  7

// ---------------- scratch (static device globals; no runtime allocation) ----
__device__ float g_table[VOCAB * G4];                       // 512 KB gate table
__device__ float g_hs[(size_t)BD * TD * HID];               // 33.5 MB, layout (B,T,H)

// ---------------- packed f32x2 helpers -------------------------------------
__device__ __forceinline__ unsigned long long pk(float lo, float hi) {
    unsigned long long r;
    asm("mov.b64 %0, {%1,%2};" : "=l"(r) : "f"(lo), "f"(hi));
    return r;
}
__device__ __forceinline__ void upk(unsigned long long p, float& lo, float& hi) {
    asm("mov.b64 {%0,%1}, %2;" : "=f"(lo), "=f"(hi) : "l"(p));
}
__device__ __forceinline__ unsigned long long fma2(unsigned long long a,
                                                   unsigned long long b,
                                                   unsigned long long c) {
    unsigned long long d;
    asm("fma.rn.f32x2 %0, %1, %2, %3;" : "=l"(d) : "l"(a), "l"(b), "l"(c));
    return d;
}
__device__ __forceinline__ unsigned long long mul2(unsigned long long a,
                                                   unsigned long long b) {
    unsigned long long d;
    asm("mul.rn.f32x2 %0, %1, %2;" : "=l"(d) : "l"(a), "l"(b));
    return d;
}
__device__ __forceinline__ unsigned long long add2(unsigned long long a,
                                                   unsigned long long b) {
    unsigned long long d;
    asm("add.rn.f32x2 %0, %1, %2;" : "=l"(d) : "l"(a), "l"(b));
    return d;
}
__device__ __forceinline__ float tanh_ap(float x) {
    float y;
    asm("tanh.approx.f32 %0, %1;" : "=f"(y) : "f"(x));
    return y;
}
__device__ __forceinline__ unsigned long long tanh2(unsigned long long p) {
    float a, b; upk(p, a, b);
    return pk(tanh_ap(a), tanh_ap(b));
}
#define HALF2 0x3F0000003F000000ULL
#define ONE2  0x3F8000003F800000ULL

// ---------------- K0: gate table  table[v][g] = emb[v]·W_ih[g] + b_ih + b_hh
// 125 CTAs x 256 threads; 8 vocab rows per CTA, all loads vectorized LDG.128.
__global__ __launch_bounds__(256, 1)
void table_kernel(const float* __restrict__ emb,
                  const float* __restrict__ W_ih,
                  const float* __restrict__ b_ih,
                  const float* __restrict__ b_hh) {
    int tid  = threadIdx.x;
    int r    = tid & 127;        // gate row 0..127
    int slot = tid >> 7;         // 0..1
    int v0   = blockIdx.x * 8;

    // W_ih row in registers (8 x LDG.128)
    float4 w[8];
    const float4* wr = (const float4*)(W_ih + r * EMBD);
#pragma unroll
    for (int i = 0; i < 8; i++) w[i] = __ldg(wr + i);
    float bias = __ldg(b_ih + r) + __ldg(b_hh + r);

#pragma unroll
    for (int vo = 0; vo < 4; vo++) {
        int v = v0 + vo * 2 + slot;
        const float4* er = (const float4*)(emb + v * EMBD);
        float a0 = bias, a1 = 0.f, a2 = 0.f, a3 = 0.f;
#pragma unroll
        for (int i = 0; i < 8; i += 4) {
            float4 e0 = __ldg(er + i + 0);
            float4 e1 = __ldg(er + i + 1);
            float4 e2 = __ldg(er + i + 2);
            float4 e3 = __ldg(er + i + 3);
            a0 += w[i + 0].x * e0.x + w[i + 0].y * e0.y + w[i + 0].z * e0.z + w[i + 0].w * e0.w;
            a1 += w[i + 1].x * e1.x + w[i + 1].y * e1.y + w[i + 1].z * e1.z + w[i + 1].w * e1.w;
            a2 += w[i + 2].x * e2.x + w[i + 2].y * e2.y + w[i + 2].z * e2.z + w[i + 2].w * e2.w;
            a3 += w[i + 3].x * e3.x + w[i + 3].y * e3.y + w[i + 3].z * e3.z + w[i + 3].w * e3.w;
        }
        g_table[v * G4 + r] = (a0 + a1) + (a2 + a3);
    }
}

// ---------------- K1: LSTM recurrence, f32x2 over batch pairs ---------------
// Grid: BD/4 CTAs x 256 threads. Each 128-thread group = 2 batch elements.
// gate = wt&3, unit = wt>>2 (gate quads within warp). Dot product split into
// 4 independent FFMA2 chains; activations branchless via per-lane constants.
__global__ __launch_bounds__(256, 1)
void lstm_kernel(const int* __restrict__ x, const float* __restrict__ W_hh) {
    __shared__ __align__(16) unsigned long long hbuf[2][2][HID]; // [grp][parity][unit]
    int tid  = threadIdx.x;
    int grp  = tid >> 7;
    int wt   = tid & 127;
    int gate = wt & 3;
    int unit = wt >> 2;
    int wrow = gate * HID + unit;          // PyTorch gate order rows: i,f,g,o
    int b0   = blockIdx.x * 4 + grp * 2;
    int b1   = b0 + 1;

    // branchless activation constants:
    //   gate==2 (tanh):    a = tanh(1.0*acc)*1.0 + 0.0
    //   else   (sigmoid):  a = tanh(0.5*acc)*0.5 + 0.5
    unsigned long long sc2 = (gate == 2) ? ONE2 : HALF2;
    unsigned long long bb2 = (gate == 2) ? 0ull : HALF2;

    // W_hh row, packed (w,w)
    unsigned long long Wp[HID];
#pragma unroll
    for (int k = 0; k < HID; k++) {
        float w = W_hh[wrow * HID + k];
        Wp[k] = pk(w, w);
    }

    if (wt < HID) { hbuf[grp][0][wt] = 0ull; hbuf[grp][1][wt] = 0ull; }
    unsigned long long c2 = 0ull;

    // index pipeline (depth 3) + xg pipeline (depth 2) to hide L2 latency
    int i0a = x[0 * BD + b0], i0b = x[0 * BD + b1];
    int i1a = x[1 * BD + b0], i1b = x[1 * BD + b1];
    int I2a = x[2 * BD + b0], I2b = x[2 * BD + b1];
    int I3a = x[3 * BD + b0], I3b = x[3 * BD + b1];
    int I4a = x[4 * BD + b0], I4b = x[4 * BD + b1];
    unsigned long long XG0 = pk(g_table[i0a * G4 + wrow], g_table[i0b * G4 + wrow]);
    unsigned long long XG1 = pk(g_table[i1a * G4 + wrow], g_table[i1b * G4 + wrow]);

    float* hsA = g_hs + (size_t)b0 * TD * HID;
    float* hsB = g_hs + (size_t)b1 * TD * HID;
    int lbase = (wt & 31) & ~3;   // lane base of this unit's gate quad
    __syncthreads();

    for (int t = 0; t < TD; t++) {
        // prefetch: idx for t+5, xg for t+2
        int nIa = 0, nIb = 0;
        if (t + 5 < TD) { nIa = x[(t + 5) * BD + b0]; nIb = x[(t + 5) * BD + b1]; }
        float nxa = g_table[I2a * G4 + wrow];
        float nxb = g_table[I2b * G4 + wrow];

        // gate pre-activation: xg + W_hh_row · h  (4 independent FFMA2 chains)
        const ulonglong2* hv2 = (const ulonglong2*)hbuf[grp][t & 1];
        unsigned long long a0 = XG0, a1 = 0ull, aa2 = 0ull, a3 = 0ull;
#pragma unroll
        for (int k = 0; k < HID / 4; k++) {
            ulonglong2 h01 = hv2[2 * k + 0];
            ulonglong2 h23 = hv2[2 * k + 1];
            a0  = fma2(Wp[4 * k + 0], h01.x, a0);
            a1  = fma2(Wp[4 * k + 1], h01.y, a1);
            aa2 = fma2(Wp[4 * k + 2], h23.x, aa2);
            a3  = fma2(Wp[4 * k + 3], h23.y, a3);
        }
        unsigned long long acc = add2(add2(a0, a1), add2(aa2, a3));

        // branchless activation
        unsigned long long a2 = fma2(tanh2(mul2(acc, sc2)), sc2, bb2);

        // gather i,f,g,o of this unit from the 4-lane quad
        unsigned long long iv = __shfl_sync(0xffffffffu, a2, lbase + 0);
        unsigned long long fv = __shfl_sync(0xffffffffu, a2, lbase + 1);
        unsigned long long gv = __shfl_sync(0xffffffffu, a2, lbase + 2);
        unsigned long long ov = __shfl_sync(0xffffffffu, a2, lbase + 3);

        c2 = fma2(fv, c2, mul2(iv, gv));                 // c = f*c + i*g
        unsigned long long hn = mul2(ov, tanh2(c2));     // h = o*tanh(c)

        if (gate == 0) {
            hbuf[grp][(t + 1) & 1][unit] = hn;           // write NEXT parity
            float ha, hb; upk(hn, ha, hb);
            hsA[t * HID + unit] = ha;
            hsB[t * HID + unit] = hb;
        }
        __syncthreads();

        XG0 = XG1; XG1 = pk(nxa, nxb);
        I2a = I3a; I2b = I3b; I3a = I4a; I3b = I4b; I4a = nIa; I4b = nIb;
    }
}

// ---------------- K2: fused FF head + softmax over T ------------------------
__global__ __launch_bounds__(256, 1)
void head_softmax_kernel(const float* __restrict__ W1, const float* __restrict__ b1,
                         const float* __restrict__ W2, const float* __restrict__ b2,
                         float* __restrict__ out) {
    __shared__ unsigned long long W1p[FF * HID];
    __shared__ unsigned long long W2p[NCLS * FF];
    __shared__ float b1s[FF], b2s[NCLS];
    __shared__ float wredm[8][NCLS], wreds[8][NCLS];

    int tid = threadIdx.x;
    for (int i = tid; i < FF * HID; i += 256) { float w = W1[i]; W1p[i] = pk(w, w); }
    if (tid < NCLS * FF) { float w = W2[tid]; W2p[tid] = pk(w, w); }
    if (tid < FF)   b1s[tid] = b1[tid];
    if (tid < NCLS) b2s[tid] = b2[tid];
    __syncthreads();

    int b  = blockIdx.x;
    int t0 = tid * 2;
    const float* hr = g_hs + ((size_t)b * TD + t0) * HID;

    unsigned long long h2[HID];
#pragma unroll
    for (int k4 = 0; k4 < HID / 4; k4++) {
        float4 u = ((const float4*)hr)[k4];
        float4 v = ((const float4*)(hr + HID))[k4];
        h2[k4 * 4 + 0] = pk(u.x, v.x);
        h2[k4 * 4 + 1] = pk(u.y, v.y);
        h2[k4 * 4 + 2] = pk(u.z, v.z);
        h2[k4 * 4 + 3] = pk(u.w, v.w);
    }

    unsigned long long z2[FF];
#pragma unroll
    for (int f = 0; f < FF; f++) {
        unsigned long long acc = pk(b1s[f], b1s[f]);
#pragma unroll
        for (int k = 0; k < HID; k++) acc = fma2(W1p[f * HID + k], h2[k], acc);
        float lo, hi; upk(acc, lo, hi);
        z2[f] = pk(fmaxf(lo, 0.f), fmaxf(hi, 0.f));
    }

    float va[NCLS], vb[NCLS];
#pragma unroll
    for (int c = 0; c < NCLS; c++) {
        unsigned long long acc = pk(b2s[c], b2s[c]);
#pragma unroll
        for (int k = 0; k < FF; k++) acc = fma2(W2p[c * FF + k], z2[k], acc);
        upk(acc, va[c], vb[c]);
    }

    // --- softmax over T (across the whole CTA) ---
    int wid = tid >> 5, lid = tid & 31;
    float vm[NCLS];
#pragma unroll
    for (int c = 0; c < NCLS; c++) vm[c] = fmaxf(va[c], vb[c]);
#pragma unroll
    for (int off = 16; off; off >>= 1)
#pragma unroll
        for (int c = 0; c < NCLS; c++)
            vm[c] = fmaxf(vm[c], __shfl_xor_sync(0xffffffffu, vm[c], off));
    if (lid == 0)
#pragma unroll
        for (int c = 0; c < NCLS; c++) wredm[wid][c] = vm[c];
    __syncthreads();
    float gmax[NCLS];
#pragma unroll
    for (int c = 0; c < NCLS; c++) {
        float m = wredm[0][c];
#pragma unroll
        for (int w = 1; w < 8; w++) m = fmaxf(m, wredm[w][c]);
        gmax[c] = m;
    }
    float sm[NCLS];
#pragma unroll
    for (int c = 0; c < NCLS; c++) {
        va[c] = __expf(va[c] - gmax[c]);
        vb[c] = __expf(vb[c] - gmax[c]);
        sm[c] = va[c] + vb[c];
    }
#pragma unroll
    for (int off = 16; off; off >>= 1)
#pragma unroll
        for (int c = 0; c < NCLS; c++)
            sm[c] += __shfl_xor_sync(0xffffffffu, sm[c], off);
    if (lid == 0)
#pragma unroll
        for (int c = 0; c < NCLS; c++) wreds[wid][c] = sm[c];
    __syncthreads();
    float inv[NCLS];
#pragma unroll
    for (int c = 0; c < NCLS; c++) {
        float s = wreds[0][c];
#pragma unroll
        for (int w = 1; w < 8; w++) s += wreds[w][c];
        inv[c] = 1.0f / s;
    }

    // out layout (T, B, NCLS)
    float* o0 = out + (size_t)t0 * BD * NCLS + (size_t)b * NCLS;
#pragma unroll
    for (int c = 0; c < NCLS; c++) o0[c] = va[c] * inv[c];
#pragma unroll
    for (int c = 0; c < NCLS; c++) o0[BD * NCLS + c] = vb[c] * inv[c];
}

// ---------------- launch -----------------------------------------------------
extern "C" void kernel_launch(void* const* d_in, const int* in_sizes, int n_in,
                              void* d_out, int out_size) {
    (void)in_sizes; (void)n_in; (void)out_size;
    const int*   x    = (const int*)  d_in[0];
    const float* emb  = (const float*)d_in[1];
    const float* W_ih = (const float*)d_in[2];
    const float* W_hh = (const float*)d_in[3];
    const float* b_ih = (const float*)d_in[4];
    const float* b_hh = (const float*)d_in[5];
    const float* W1   = (const float*)d_in[6];
    const float* b1   = (const float*)d_in[7];
    const float* W2   = (const float*)d_in[8];
    const float* b2   = (const float*)d_in[9];

    table_kernel<<<VOCAB / 8, 256>>>(emb, W_ih, b_ih, b_hh);
    lstm_kernel<<<BD / 4, 256>>>(x, W_hh);
    head_softmax_kernel<<<BD, 256>>>(W1, b1, W2, b2, (float*)d_out);
}

// round 3
// speedup vs baseline: 1.1642x; 1.1642x over previous
#include <cuda_runtime.h>

#define TD    512   // timesteps
#define BD    512   // batch
#define HID   32    // hidden
#define G4    128   // 4*HID gate rows
#define EMBD  32
#define VOCAB 1000
#define FF    16
#define NCLS  7

// ---------------- scratch (static device globals; no runtime allocation) ----
__device__ float g_table[VOCAB * G4];                       // 512 KB gate table
__device__ float g_hs[(size_t)BD * TD * HID];               // 33.5 MB, layout (B,T,H)

// ---------------- packed f32x2 helpers -------------------------------------
__device__ __forceinline__ unsigned long long pk(float lo, float hi) {
    unsigned long long r;
    asm("mov.b64 %0, {%1,%2};" : "=l"(r) : "f"(lo), "f"(hi));
    return r;
}
__device__ __forceinline__ void upk(unsigned long long p, float& lo, float& hi) {
    asm("mov.b64 {%0,%1}, %2;" : "=f"(lo), "=f"(hi) : "l"(p));
}
__device__ __forceinline__ unsigned long long fma2(unsigned long long a,
                                                   unsigned long long b,
                                                   unsigned long long c) {
    unsigned long long d;
    asm("fma.rn.f32x2 %0, %1, %2, %3;" : "=l"(d) : "l"(a), "l"(b), "l"(c));
    return d;
}
__device__ __forceinline__ unsigned long long mul2(unsigned long long a,
                                                   unsigned long long b) {
    unsigned long long d;
    asm("mul.rn.f32x2 %0, %1, %2;" : "=l"(d) : "l"(a), "l"(b));
    return d;
}
__device__ __forceinline__ unsigned long long add2(unsigned long long a,
                                                   unsigned long long b) {
    unsigned long long d;
    asm("add.rn.f32x2 %0, %1, %2;" : "=l"(d) : "l"(a), "l"(b));
    return d;
}
__device__ __forceinline__ float tanh_ap(float x) {
    float y;
    asm("tanh.approx.f32 %0, %1;" : "=f"(y) : "f"(x));
    return y;
}
__device__ __forceinline__ unsigned long long tanh2(unsigned long long p) {
    float a, b; upk(p, a, b);
    return pk(tanh_ap(a), tanh_ap(b));
}
#define HALF2 0x3F0000003F000000ULL
#define ONE2  0x3F8000003F800000ULL

// group-scoped named barrier: 128 threads, barrier id = grp+1
__device__ __forceinline__ void group_bar(int grp) {
    asm volatile("bar.sync %0, %1;" :: "r"(grp + 1), "r"(128) : "memory");
}

// ---------------- K0: gate table  table[v][g] = emb[v]·W_ih[g] + b_ih + b_hh
__global__ __launch_bounds__(256, 1)
void table_kernel(const float* __restrict__ emb,
                  const float* __restrict__ W_ih,
                  const float* __restrict__ b_ih,
                  const float* __restrict__ b_hh) {
    int tid  = threadIdx.x;
    int r    = tid & 127;        // gate row 0..127
    int slot = tid >> 7;         // 0..1
    int v0   = blockIdx.x * 8;

    float4 w[8];
    const float4* wr = (const float4*)(W_ih + r * EMBD);
#pragma unroll
    for (int i = 0; i < 8; i++) w[i] = __ldg(wr + i);
    float bias = __ldg(b_ih + r) + __ldg(b_hh + r);

#pragma unroll
    for (int vo = 0; vo < 4; vo++) {
        int v = v0 + vo * 2 + slot;
        const float4* er = (const float4*)(emb + v * EMBD);
        float a0 = bias, a1 = 0.f, a2 = 0.f, a3 = 0.f;
#pragma unroll
        for (int i = 0; i < 8; i += 4) {
            float4 e0 = __ldg(er + i + 0);
            float4 e1 = __ldg(er + i + 1);
            float4 e2 = __ldg(er + i + 2);
            float4 e3 = __ldg(er + i + 3);
            a0 += w[i + 0].x * e0.x + w[i + 0].y * e0.y + w[i + 0].z * e0.z + w[i + 0].w * e0.w;
            a1 += w[i + 1].x * e1.x + w[i + 1].y * e1.y + w[i + 1].z * e1.z + w[i + 1].w * e1.w;
            a2 += w[i + 2].x * e2.x + w[i + 2].y * e2.y + w[i + 2].z * e2.z + w[i + 2].w * e2.w;
            a3 += w[i + 3].x * e3.x + w[i + 3].y * e3.y + w[i + 3].z * e3.z + w[i + 3].w * e3.w;
        }
        g_table[v * G4 + r] = (a0 + a1) + (a2 + a3);
    }
}

// ---------------- K1: LSTM recurrence, f32x2 over batch pairs ---------------
// Grid: BD/4 CTAs x 256 threads. Each 128-thread group = 2 batch elements.
// Groups are DECOUPLED: each group syncs only its own 4 warps via a named
// barrier, so the SMSP interleaves two independent recurrence chains.
__global__ __launch_bounds__(256, 1)
void lstm_kernel(const int* __restrict__ x, const float* __restrict__ W_hh) {
    __shared__ __align__(16) unsigned long long hbuf[2][2][HID]; // [grp][parity][unit]
    int tid  = threadIdx.x;
    int grp  = tid >> 7;
    int wt   = tid & 127;
    int gate = wt & 3;
    int unit = wt >> 2;
    int wrow = gate * HID + unit;          // PyTorch gate order rows: i,f,g,o
    int b0   = blockIdx.x * 4 + grp * 2;
    int b1   = b0 + 1;

    // branchless activation constants:
    //   gate==2 (tanh):    a = tanh(1.0*acc)*1.0 + 0.0
    //   else   (sigmoid):  a = tanh(0.5*acc)*0.5 + 0.5
    unsigned long long sc2 = (gate == 2) ? ONE2 : HALF2;
    unsigned long long bb2 = (gate == 2) ? 0ull : HALF2;

    // W_hh row, packed (w,w)
    unsigned long long Wp[HID];
#pragma unroll
    for (int k = 0; k < HID; k++) {
        float w = W_hh[wrow * HID + k];
        Wp[k] = pk(w, w);
    }

    if (wt < HID) { hbuf[grp][0][wt] = 0ull; hbuf[grp][1][wt] = 0ull; }
    unsigned long long c2 = 0ull;

    // index pipeline (depth 3) + xg pipeline (depth 2) to hide L2 latency
    int i0a = x[0 * BD + b0], i0b = x[0 * BD + b1];
    int i1a = x[1 * BD + b0], i1b = x[1 * BD + b1];
    int I2a = x[2 * BD + b0], I2b = x[2 * BD + b1];
    int I3a = x[3 * BD + b0], I3b = x[3 * BD + b1];
    int I4a = x[4 * BD + b0], I4b = x[4 * BD + b1];
    unsigned long long XG0 = pk(g_table[i0a * G4 + wrow], g_table[i0b * G4 + wrow]);
    unsigned long long XG1 = pk(g_table[i1a * G4 + wrow], g_table[i1b * G4 + wrow]);

    float* hsA = g_hs + (size_t)b0 * TD * HID;
    float* hsB = g_hs + (size_t)b1 * TD * HID;
    int lbase = (wt & 31) & ~3;   // lane base of this unit's gate quad
    group_bar(grp);

    for (int t = 0; t < TD; t++) {
        // prefetch: idx for t+5, xg for t+2
        int nIa = 0, nIb = 0;
        if (t + 5 < TD) { nIa = x[(t + 5) * BD + b0]; nIb = x[(t + 5) * BD + b1]; }
        float nxa = g_table[I2a * G4 + wrow];
        float nxb = g_table[I2b * G4 + wrow];

        // gate pre-activation: xg + W_hh_row · h  (4 independent FFMA2 chains)
        const ulonglong2* hv2 = (const ulonglong2*)hbuf[grp][t & 1];
        unsigned long long a0 = XG0, a1 = 0ull, aa2 = 0ull, a3 = 0ull;
#pragma unroll
        for (int k = 0; k < HID / 4; k++) {
            ulonglong2 h01 = hv2[2 * k + 0];
            ulonglong2 h23 = hv2[2 * k + 1];
            a0  = fma2(Wp[4 * k + 0], h01.x, a0);
            a1  = fma2(Wp[4 * k + 1], h01.y, a1);
            aa2 = fma2(Wp[4 * k + 2], h23.x, aa2);
            a3  = fma2(Wp[4 * k + 3], h23.y, a3);
        }
        unsigned long long acc = add2(add2(a0, a1), add2(aa2, a3));

        // branchless activation
        unsigned long long a2 = fma2(tanh2(mul2(acc, sc2)), sc2, bb2);

        // gather i,f,g,o of this unit from the 4-lane quad
        unsigned long long iv = __shfl_sync(0xffffffffu, a2, lbase + 0);
        unsigned long long fv = __shfl_sync(0xffffffffu, a2, lbase + 1);
        unsigned long long gv = __shfl_sync(0xffffffffu, a2, lbase + 2);
        unsigned long long ov = __shfl_sync(0xffffffffu, a2, lbase + 3);

        c2 = fma2(fv, c2, mul2(iv, gv));                 // c = f*c + i*g
        unsigned long long hn = mul2(ov, tanh2(c2));     // h = o*tanh(c)

        if (gate == 0) {
            hbuf[grp][(t + 1) & 1][unit] = hn;           // write NEXT parity
            float ha, hb; upk(hn, ha, hb);
            hsA[t * HID + unit] = ha;
            hsB[t * HID + unit] = hb;
        }
        group_bar(grp);

        XG0 = XG1; XG1 = pk(nxa, nxb);
        I2a = I3a; I2b = I3b; I3a = I4a; I3b = I4b; I4a = nIa; I4b = nIb;
    }
}

// ---------------- K2: fused FF head + softmax over T ------------------------
__global__ __launch_bounds__(256, 1)
void head_softmax_kernel(const float* __restrict__ W1, const float* __restrict__ b1,
                         const float* __restrict__ W2, const float* __restrict__ b2,
                         float* __restrict__ out) {
    __shared__ unsigned long long W1p[FF * HID];
    __shared__ unsigned long long W2p[NCLS * FF];
    __shared__ float b1s[FF], b2s[NCLS];
    __shared__ float wredm[8][NCLS], wreds[8][NCLS];

    int tid = threadIdx.x;
    for (int i = tid; i < FF * HID; i += 256) { float w = W1[i]; W1p[i] = pk(w, w); }
    if (tid < NCLS * FF) { float w = W2[tid]; W2p[tid] = pk(w, w); }
    if (tid < FF)   b1s[tid] = b1[tid];
    if (tid < NCLS) b2s[tid] = b2[tid];
    __syncthreads();

    int b  = blockIdx.x;
    int t0 = tid * 2;
    const float* hr = g_hs + ((size_t)b * TD + t0) * HID;

    unsigned long long h2[HID];
#pragma unroll
    for (int k4 = 0; k4 < HID / 4; k4++) {
        float4 u = ((const float4*)hr)[k4];
        float4 v = ((const float4*)(hr + HID))[k4];
        h2[k4 * 4 + 0] = pk(u.x, v.x);
        h2[k4 * 4 + 1] = pk(u.y, v.y);
        h2[k4 * 4 + 2] = pk(u.z, v.z);
        h2[k4 * 4 + 3] = pk(u.w, v.w);
    }

    unsigned long long z2[FF];
#pragma unroll
    for (int f = 0; f < FF; f++) {
        unsigned long long acc = pk(b1s[f], b1s[f]);
#pragma unroll
        for (int k = 0; k < HID; k++) acc = fma2(W1p[f * HID + k], h2[k], acc);
        float lo, hi; upk(acc, lo, hi);
        z2[f] = pk(fmaxf(lo, 0.f), fmaxf(hi, 0.f));
    }

    float va[NCLS], vb[NCLS];
#pragma unroll
    for (int c = 0; c < NCLS; c++) {
        unsigned long long acc = pk(b2s[c], b2s[c]);
#pragma unroll
        for (int k = 0; k < FF; k++) acc = fma2(W2p[c * FF + k], z2[k], acc);
        upk(acc, va[c], vb[c]);
    }

    // --- softmax over T (across the whole CTA) ---
    int wid = tid >> 5, lid = tid & 31;
    float vm[NCLS];
#pragma unroll
    for (int c = 0; c < NCLS; c++) vm[c] = fmaxf(va[c], vb[c]);
#pragma unroll
    for (int off = 16; off; off >>= 1)
#pragma unroll
        for (int c = 0; c < NCLS; c++)
            vm[c] = fmaxf(vm[c], __shfl_xor_sync(0xffffffffu, vm[c], off));
    if (lid == 0)
#pragma unroll
        for (int c = 0; c < NCLS; c++) wredm[wid][c] = vm[c];
    __syncthreads();
    float gmax[NCLS];
#pragma unroll
    for (int c = 0; c < NCLS; c++) {
        float m = wredm[0][c];
#pragma unroll
        for (int w = 1; w < 8; w++) m = fmaxf(m, wredm[w][c]);
        gmax[c] = m;
    }
    float sm[NCLS];
#pragma unroll
    for (int c = 0; c < NCLS; c++) {
        va[c] = __expf(va[c] - gmax[c]);
        vb[c] = __expf(vb[c] - gmax[c]);
        sm[c] = va[c] + vb[c];
    }
#pragma unroll
    for (int off = 16; off; off >>= 1)
#pragma unroll
        for (int c = 0; c < NCLS; c++)
            sm[c] += __shfl_xor_sync(0xffffffffu, sm[c], off);
    if (lid == 0)
#pragma unroll
        for (int c = 0; c < NCLS; c++) wreds[wid][c] = sm[c];
    __syncthreads();
    float inv[NCLS];
#pragma unroll
    for (int c = 0; c < NCLS; c++) {
        float s = wreds[0][c];
#pragma unroll
        for (int w = 1; w < 8; w++) s += wreds[w][c];
        inv[c] = 1.0f / s;
    }

    // out layout (T, B, NCLS)
    float* o0 = out + (size_t)t0 * BD * NCLS + (size_t)b * NCLS;
#pragma unroll
    for (int c = 0; c < NCLS; c++) o0[c] = va[c] * inv[c];
#pragma unroll
    for (int c = 0; c < NCLS; c++) o0[BD * NCLS + c] = vb[c] * inv[c];
}

// ---------------- launch -----------------------------------------------------
extern "C" void kernel_launch(void* const* d_in, const int* in_sizes, int n_in,
                              void* d_out, int out_size) {
    (void)in_sizes; (void)n_in; (void)out_size;
    const int*   x    = (const int*)  d_in[0];
    const float* emb  = (const float*)d_in[1];
    const float* W_ih = (const float*)d_in[2];
    const float* W_hh = (const float*)d_in[3];
    const float* b_ih = (const float*)d_in[4];
    const float* b_hh = (const float*)d_in[5];
    const float* W1   = (const float*)d_in[6];
    const float* b1   = (const float*)d_in[7];
    const float* W2   = (const float*)d_in[8];
    const float* b2   = (const float*)d_in[9];

    table_kernel<<<VOCAB / 8, 256>>>(emb, W_ih, b_ih, b_hh);
    lstm_kernel<<<BD / 4, 256>>>(x, W_hh);
    head_softmax_kernel<<<BD, 256>>>(W1, b1, W2, b2, (float*)d_out);
}

// round 4
// speedup vs baseline: 1.4557x; 1.2504x over previous
#include <cuda_runtime.h>

#define TD    512   // timesteps
#define BD    512   // batch
#define HID   32    // hidden
#define G4    128   // 4*HID gate rows
#define EMBD  32
#define VOCAB 1000
#define FF    16
#define NCLS  7

// ---------------- scratch (static device globals; no runtime allocation) ----
// table layout: [v][unit][gate i,f,g,o]  (float4 per unit)
__device__ float g_table[VOCAB * G4];                       // 512 KB
__device__ float g_hs[(size_t)BD * TD * HID];               // 33.5 MB, (B,T,H)

// ---------------- packed f32x2 helpers -------------------------------------
__device__ __forceinline__ unsigned long long pk(float lo, float hi) {
    unsigned long long r;
    asm("mov.b64 %0, {%1,%2};" : "=l"(r) : "f"(lo), "f"(hi));
    return r;
}
__device__ __forceinline__ void upk(unsigned long long p, float& lo, float& hi) {
    asm("mov.b64 {%0,%1}, %2;" : "=f"(lo), "=f"(hi) : "l"(p));
}
__device__ __forceinline__ unsigned long long fma2(unsigned long long a,
                                                   unsigned long long b,
                                                   unsigned long long c) {
    unsigned long long d;
    asm("fma.rn.f32x2 %0, %1, %2, %3;" : "=l"(d) : "l"(a), "l"(b), "l"(c));
    return d;
}
__device__ __forceinline__ unsigned long long mul2(unsigned long long a,
                                                   unsigned long long b) {
    unsigned long long d;
    asm("mul.rn.f32x2 %0, %1, %2;" : "=l"(d) : "l"(a), "l"(b));
    return d;
}
__device__ __forceinline__ unsigned long long add2(unsigned long long a,
                                                   unsigned long long b) {
    unsigned long long d;
    asm("add.rn.f32x2 %0, %1, %2;" : "=l"(d) : "l"(a), "l"(b));
    return d;
}
__device__ __forceinline__ float tanh_ap(float x) {
    float y;
    asm("tanh.approx.f32 %0, %1;" : "=f"(y) : "f"(x));
    return y;
}
__device__ __forceinline__ unsigned long long tanh2(unsigned long long p) {
    float a, b; upk(p, a, b);
    return pk(tanh_ap(a), tanh_ap(b));
}
#define HALF2  0x3F0000003F000000ULL   // (0.5, 0.5)
#define SC_GO  0x3F0000003F800000ULL   // (1.0, 0.5)  g:tanh scale, o:sigmoid scale
#define BI_GO  0x3F00000000000000ULL   // (0.0, 0.5)

// ---------------- K0: gate table  table[v][unit][gate] ----------------------
__global__ __launch_bounds__(256, 1)
void table_kernel(const float* __restrict__ emb,
                  const float* __restrict__ W_ih,
                  const float* __restrict__ b_ih,
                  const float* __restrict__ b_hh) {
    int tid  = threadIdx.x;
    int r    = tid & 127;        // gate-major row: gate = r>>5, unit = r&31
    int slot = tid >> 7;
    int v0   = blockIdx.x * 8;
    int gate = r >> 5, unit = r & 31;

    float4 w[8];
    const float4* wr = (const float4*)(W_ih + r * EMBD);
#pragma unroll
    for (int i = 0; i < 8; i++) w[i] = __ldg(wr + i);
    float bias = __ldg(b_ih + r) + __ldg(b_hh + r);

#pragma unroll
    for (int vo = 0; vo < 4; vo++) {
        int v = v0 + vo * 2 + slot;
        const float4* er = (const float4*)(emb + v * EMBD);
        float a0 = bias, a1 = 0.f, a2 = 0.f, a3 = 0.f;
#pragma unroll
        for (int i = 0; i < 8; i += 4) {
            float4 e0 = __ldg(er + i + 0);
            float4 e1 = __ldg(er + i + 1);
            float4 e2 = __ldg(er + i + 2);
            float4 e3 = __ldg(er + i + 3);
            a0 += w[i + 0].x * e0.x + w[i + 0].y * e0.y + w[i + 0].z * e0.z + w[i + 0].w * e0.w;
            a1 += w[i + 1].x * e1.x + w[i + 1].y * e1.y + w[i + 1].z * e1.z + w[i + 1].w * e1.w;
            a2 += w[i + 2].x * e2.x + w[i + 2].y * e2.y + w[i + 2].z * e2.z + w[i + 2].w * e2.w;
            a3 += w[i + 3].x * e3.x + w[i + 3].y * e3.y + w[i + 3].z * e3.z + w[i + 3].w * e3.w;
        }
        // store at [v][unit][gate]
        g_table[v * G4 + unit * 4 + gate] = (a0 + a1) + (a2 + a3);
    }
}

// ---------------- K1: LSTM — one warp per batch element ---------------------
// lane = hidden unit. Gates packed per lane: (i,f) and (g,o) f32x2 chains.
// h exchanged via per-warp smem double buffer + __syncwarp — no barriers,
// no cross-SMSP coupling. 128 CTAs x 128 thr = 512 warps = ~1/SMSP chip-wide.
__global__ __launch_bounds__(128, 1)
void lstm_kernel(const int* __restrict__ x, const float* __restrict__ W_hh) {
    __shared__ __align__(16) unsigned long long hbuf[4][2][HID]; // [warp][parity][unit]
    int warp = threadIdx.x >> 5;
    int lane = threadIdx.x & 31;
    int b    = blockIdx.x * 4 + warp;

    // ---- weights: rows i,f,g,o for this unit, packed (wi,wf) / (wg,wo) ----
    unsigned long long Wif[HID], Wgo[HID];
    {
        float4 ri[8], rf[8], rg[8], ro[8];
        const float4* pi = (const float4*)(W_hh + (0 * HID + lane) * HID);
        const float4* pf = (const float4*)(W_hh + (1 * HID + lane) * HID);
        const float4* pg = (const float4*)(W_hh + (2 * HID + lane) * HID);
        const float4* po = (const float4*)(W_hh + (3 * HID + lane) * HID);
#pragma unroll
        for (int i = 0; i < 8; i++) { ri[i] = __ldg(pi + i); rf[i] = __ldg(pf + i); }
#pragma unroll
        for (int i = 0; i < 8; i++) {
            Wif[4 * i + 0] = pk(ri[i].x, rf[i].x);
            Wif[4 * i + 1] = pk(ri[i].y, rf[i].y);
            Wif[4 * i + 2] = pk(ri[i].z, rf[i].z);
            Wif[4 * i + 3] = pk(ri[i].w, rf[i].w);
        }
#pragma unroll
        for (int i = 0; i < 8; i++) { rg[i] = __ldg(pg + i); ro[i] = __ldg(po + i); }
#pragma unroll
        for (int i = 0; i < 8; i++) {
            Wgo[4 * i + 0] = pk(rg[i].x, ro[i].x);
            Wgo[4 * i + 1] = pk(rg[i].y, ro[i].y);
            Wgo[4 * i + 2] = pk(rg[i].z, ro[i].z);
            Wgo[4 * i + 3] = pk(rg[i].w, ro[i].w);
        }
    }

    // zero h buffer (parity 0 read at t=0)
    hbuf[warp][0][lane] = 0ull;
    hbuf[warp][1][lane] = 0ull;
    __syncwarp();

    const float4* tab4 = (const float4*)g_table;   // 32 float4 per vocab row

    // pipelines: index depth 6 (I3..I5 live), xg depth 3
    int I3 = x[0 * BD + b];
    int I4 = x[1 * BD + b];
    int I5 = x[2 * BD + b];
    float4 XG0 = __ldg(tab4 + I3 * 32 + lane);   // t=0
    float4 XG1 = __ldg(tab4 + I4 * 32 + lane);   // t=1
    float4 XG2 = __ldg(tab4 + I5 * 32 + lane);   // t=2
    I3 = x[3 * BD + b];
    I4 = x[4 * BD + b];
    I5 = x[5 * BD + b];

    float c = 0.f;
    float* hs = g_hs + (size_t)b * TD * HID;

    for (int t = 0; t < TD; t++) {
        // prefetch xg for t+3 (2 bodies of slack), index for t+6
        float4 nxg = __ldg(tab4 + I3 * 32 + lane);
        int nI = 0;
        if (t + 6 < TD) nI = x[(t + 6) * BD + b];

        // gate pre-activation: 4+4 independent FFMA2 chains over h
        unsigned long long aif0 = pk(XG0.x, XG0.y), aif1 = 0ull, aif2 = 0ull, aif3 = 0ull;
        unsigned long long ago0 = pk(XG0.z, XG0.w), ago1 = 0ull, ago2 = 0ull, ago3 = 0ull;
        const ulonglong2* hv = (const ulonglong2*)hbuf[warp][t & 1];
#pragma unroll
        for (int m = 0; m < HID / 2; m += 2) {      // 16 LDS.128, 64 FFMA2
            ulonglong2 h01 = hv[m];
            ulonglong2 h23 = hv[m + 1];
            aif0 = fma2(Wif[2 * m + 0], h01.x, aif0);
            aif1 = fma2(Wif[2 * m + 1], h01.y, aif1);
            aif2 = fma2(Wif[2 * m + 2], h23.x, aif2);
            aif3 = fma2(Wif[2 * m + 3], h23.y, aif3);
            ago0 = fma2(Wgo[2 * m + 0], h01.x, ago0);
            ago1 = fma2(Wgo[2 * m + 1], h01.y, ago1);
            ago2 = fma2(Wgo[2 * m + 2], h23.x, ago2);
            ago3 = fma2(Wgo[2 * m + 3], h23.y, ago3);
        }
        unsigned long long aif = add2(add2(aif0, aif1), add2(aif2, aif3));
        unsigned long long ago = add2(add2(ago0, ago1), add2(ago2, ago3));

        // activations (branchless, packed): (i,f)=sigmoid ; (g,o)=(tanh,sigmoid)
        unsigned long long sif = fma2(tanh2(mul2(aif, HALF2)), HALF2, HALF2);
        unsigned long long sgo = fma2(tanh2(mul2(ago, SC_GO)), SC_GO, BI_GO);

        float iv, fv, gv, ov;
        upk(sif, iv, fv);
        upk(sgo, gv, ov);

        c = fmaf(fv, c, iv * gv);          // c = f*c + i*g
        float h = ov * tanh_ap(c);         // h = o*tanh(c)

        hbuf[warp][(t + 1) & 1][lane] = pk(h, h);
        hs[t * HID + lane] = h;            // coalesced 128B per warp
        __syncwarp();

        XG0 = XG1; XG1 = XG2; XG2 = nxg;
        I3 = I4; I4 = I5; I5 = nI;
    }
}

// ---------------- K2: fused FF head + softmax over T ------------------------
__global__ __launch_bounds__(256, 1)
void head_softmax_kernel(const float* __restrict__ W1, const float* __restrict__ b1,
                         const float* __restrict__ W2, const float* __restrict__ b2,
                         float* __restrict__ out) {
    __shared__ unsigned long long W1p[FF * HID];
    __shared__ unsigned long long W2p[NCLS * FF];
    __shared__ float b1s[FF], b2s[NCLS];
    __shared__ float wredm[8][NCLS], wreds[8][NCLS];

    int tid = threadIdx.x;
    for (int i = tid; i < FF * HID; i += 256) { float w = W1[i]; W1p[i] = pk(w, w); }
    if (tid < NCLS * FF) { float w = W2[tid]; W2p[tid] = pk(w, w); }
    if (tid < FF)   b1s[tid] = b1[tid];
    if (tid < NCLS) b2s[tid] = b2[tid];
    __syncthreads();

    int b  = blockIdx.x;
    int t0 = tid * 2;
    const float* hr = g_hs + ((size_t)b * TD + t0) * HID;

    unsigned long long h2[HID];
#pragma unroll
    for (int k4 = 0; k4 < HID / 4; k4++) {
        float4 u = ((const float4*)hr)[k4];
        float4 v = ((const float4*)(hr + HID))[k4];
        h2[k4 * 4 + 0] = pk(u.x, v.x);
        h2[k4 * 4 + 1] = pk(u.y, v.y);
        h2[k4 * 4 + 2] = pk(u.z, v.z);
        h2[k4 * 4 + 3] = pk(u.w, v.w);
    }

    unsigned long long z2[FF];
#pragma unroll
    for (int f = 0; f < FF; f++) {
        unsigned long long acc = pk(b1s[f], b1s[f]);
#pragma unroll
        for (int k = 0; k < HID; k++) acc = fma2(W1p[f * HID + k], h2[k], acc);
        float lo, hi; upk(acc, lo, hi);
        z2[f] = pk(fmaxf(lo, 0.f), fmaxf(hi, 0.f));
    }

    float va[NCLS], vb[NCLS];
#pragma unroll
    for (int c = 0; c < NCLS; c++) {
        unsigned long long acc = pk(b2s[c], b2s[c]);
#pragma unroll
        for (int k = 0; k < FF; k++) acc = fma2(W2p[c * FF + k], z2[k], acc);
        upk(acc, va[c], vb[c]);
    }

    // --- softmax over T (across the whole CTA) ---
    int wid = tid >> 5, lid = tid & 31;
    float vm[NCLS];
#pragma unroll
    for (int c = 0; c < NCLS; c++) vm[c] = fmaxf(va[c], vb[c]);
#pragma unroll
    for (int off = 16; off; off >>= 1)
#pragma unroll
        for (int c = 0; c < NCLS; c++)
            vm[c] = fmaxf(vm[c], __shfl_xor_sync(0xffffffffu, vm[c], off));
    if (lid == 0)
#pragma unroll
        for (int c = 0; c < NCLS; c++) wredm[wid][c] = vm[c];
    __syncthreads();
    float gmax[NCLS];
#pragma unroll
    for (int c = 0; c < NCLS; c++) {
        float m = wredm[0][c];
#pragma unroll
        for (int w = 1; w < 8; w++) m = fmaxf(m, wredm[w][c]);
        gmax[c] = m;
    }
    float sm[NCLS];
#pragma unroll
    for (int c = 0; c < NCLS; c++) {
        va[c] = __expf(va[c] - gmax[c]);
        vb[c] = __expf(vb[c] - gmax[c]);
        sm[c] = va[c] + vb[c];
    }
#pragma unroll
    for (int off = 16; off; off >>= 1)
#pragma unroll
        for (int c = 0; c < NCLS; c++)
            sm[c] += __shfl_xor_sync(0xffffffffu, sm[c], off);
    if (lid == 0)
#pragma unroll
        for (int c = 0; c < NCLS; c++) wreds[wid][c] = sm[c];
    __syncthreads();
    float inv[NCLS];
#pragma unroll
    for (int c = 0; c < NCLS; c++) {
        float s = wreds[0][c];
#pragma unroll
        for (int w = 1; w < 8; w++) s += wreds[w][c];
        inv[c] = 1.0f / s;
    }

    float* o0 = out + (size_t)t0 * BD * NCLS + (size_t)b * NCLS;
#pragma unroll
    for (int c = 0; c < NCLS; c++) o0[c] = va[c] * inv[c];
#pragma unroll
    for (int c = 0; c < NCLS; c++) o0[BD * NCLS + c] = vb[c] * inv[c];
}

// ---------------- launch -----------------------------------------------------
extern "C" void kernel_launch(void* const* d_in, const int* in_sizes, int n_in,
                              void* d_out, int out_size) {
    (void)in_sizes; (void)n_in; (void)out_size;
    const int*   x    = (const int*)  d_in[0];
    const float* emb  = (const float*)d_in[1];
    const float* W_ih = (const float*)d_in[2];
    const float* W_hh = (const float*)d_in[3];
    const float* b_ih = (const float*)d_in[4];
    const float* b_hh = (const float*)d_in[5];
    const float* W1   = (const float*)d_in[6];
    const float* b1   = (const float*)d_in[7];
    const float* W2   = (const float*)d_in[8];
    const float* b2   = (const float*)d_in[9];

    table_kernel<<<VOCAB / 8, 256>>>(emb, W_ih, b_ih, b_hh);
    lstm_kernel<<<BD / 4, 128>>>(x, W_hh);
    head_softmax_kernel<<<BD, 256>>>(W1, b1, W2, b2, (float*)d_out);
}

// round 7
// speedup vs baseline: 1.8656x; 1.2816x over previous
#include <cuda_runtime.h>
#include <cuda_fp16.h>

#define TD    512   // timesteps
#define BD    512   // batch
#define HID   32    // hidden
#define G4    128   // 4*HID gate rows
#define EMBD  32
#define VOCAB 1000
#define FF    16
#define NCLS  7

// ---------------- scratch (static device globals; no runtime allocation) ----
// table layout: [v][unit][gate i,f,g,o]  (float4 per unit)
__device__ float g_table[VOCAB * G4];                       // 512 KB
__device__ float g_hs[(size_t)BD * TD * HID];               // 33.5 MB, (B,T,H)

// ---------------- packed f32x2 helpers -------------------------------------
__device__ __forceinline__ unsigned long long pk(float lo, float hi) {
    unsigned long long r;
    asm("mov.b64 %0, {%1,%2};" : "=l"(r) : "f"(lo), "f"(hi));
    return r;
}
__device__ __forceinline__ void upk(unsigned long long p, float& lo, float& hi) {
    asm("mov.b64 {%0,%1}, %2;" : "=f"(lo), "=f"(hi) : "l"(p));
}
__device__ __forceinline__ unsigned long long fma2(unsigned long long a,
                                                   unsigned long long b,
                                                   unsigned long long c) {
    unsigned long long d;
    asm("fma.rn.f32x2 %0, %1, %2, %3;" : "=l"(d) : "l"(a), "l"(b), "l"(c));
    return d;
}
__device__ __forceinline__ unsigned long long mul2(unsigned long long a,
                                                   unsigned long long b) {
    unsigned long long d;
    asm("mul.rn.f32x2 %0, %1, %2;" : "=l"(d) : "l"(a), "l"(b));
    return d;
}
__device__ __forceinline__ float tanh_ap(float x) {
    float y;
    asm("tanh.approx.f32 %0, %1;" : "=f"(y) : "f"(x));
    return y;
}
__device__ __forceinline__ unsigned long long tanh2(unsigned long long p) {
    float a, b; upk(p, a, b);
    return pk(tanh_ap(a), tanh_ap(b));
}
#define HALF2  0x3F0000003F000000ULL   // (0.5, 0.5)
#define SC_GO  0x3F0000003F800000ULL   // (1.0, 0.5)  g:tanh scale, o:sigmoid scale
#define BI_GO  0x3F00000000000000ULL   // (0.0, 0.5)

__device__ __forceinline__ __half2 u2h2(unsigned int u) {
    return *reinterpret_cast<__half2*>(&u);
}

// ---------------- K0: gate table  table[v][unit][gate] ----------------------
__global__ __launch_bounds__(256, 1)
void table_kernel(const float* __restrict__ emb,
                  const float* __restrict__ W_ih,
                  const float* __restrict__ b_ih,
                  const float* __restrict__ b_hh) {
    int tid  = threadIdx.x;
    int r    = tid & 127;        // gate-major row: gate = r>>5, unit = r&31
    int slot = tid >> 7;
    int v0   = blockIdx.x * 8;
    int gate = r >> 5, unit = r & 31;

    float4 w[8];
    const float4* wr = (const float4*)(W_ih + r * EMBD);
#pragma unroll
    for (int i = 0; i < 8; i++) w[i] = __ldg(wr + i);
    float bias = __ldg(b_ih + r) + __ldg(b_hh + r);

#pragma unroll
    for (int vo = 0; vo < 4; vo++) {
        int v = v0 + vo * 2 + slot;
        const float4* er = (const float4*)(emb + v * EMBD);
        float a0 = bias, a1 = 0.f, a2 = 0.f, a3 = 0.f;
#pragma unroll
        for (int i = 0; i < 8; i += 4) {
            float4 e0 = __ldg(er + i + 0);
            float4 e1 = __ldg(er + i + 1);
            float4 e2 = __ldg(er + i + 2);
            float4 e3 = __ldg(er + i + 3);
            a0 += w[i + 0].x * e0.x + w[i + 0].y * e0.y + w[i + 0].z * e0.z + w[i + 0].w * e0.w;
            a1 += w[i + 1].x * e1.x + w[i + 1].y * e1.y + w[i + 1].z * e1.z + w[i + 1].w * e1.w;
            a2 += w[i + 2].x * e2.x + w[i + 2].y * e2.y + w[i + 2].z * e2.z + w[i + 2].w * e2.w;
            a3 += w[i + 3].x * e3.x + w[i + 3].y * e3.y + w[i + 3].z * e3.z + w[i + 3].w * e3.w;
        }
        g_table[v * G4 + unit * 4 + gate] = (a0 + a1) + (a2 + a3);
    }
}

// ---------------- K1: LSTM — one warp per batch element, fp16 dot -----------
// lane = hidden unit. W_hh·h in __half2 (HFMA2, rt=2 -> 2x fp32 FMA rate);
// xg, c, h state and activations stay fp32. h exchanged as half2 via per-warp
// smem double buffer + __syncwarp.
__global__ __launch_bounds__(128, 1)
void lstm_kernel(const int* __restrict__ x, const float* __restrict__ W_hh) {
    __shared__ __align__(16) __half2 hbuf[4][2][HID / 2];   // [warp][parity][pair]
    int warp = threadIdx.x >> 5;
    int lane = threadIdx.x & 31;
    int b    = blockIdx.x * 4 + warp;

    // ---- weights: rows i,f,g,o for this unit as half2 pairs over h ----
    __half2 W2[4][HID / 2];                                  // 64 regs
#pragma unroll
    for (int g = 0; g < 4; g++) {
        const float4* p = (const float4*)(W_hh + (g * HID + lane) * HID);
#pragma unroll
        for (int i = 0; i < 8; i++) {
            float4 rv = __ldg(p + i);
            W2[g][2 * i + 0] = __floats2half2_rn(rv.x, rv.y);
            W2[g][2 * i + 1] = __floats2half2_rn(rv.z, rv.w);
        }
    }

    if (lane < HID / 2) {
        hbuf[warp][0][lane] = __float2half2_rn(0.f);
        hbuf[warp][1][lane] = __float2half2_rn(0.f);
    }
    __syncwarp();

    const float4* tab4 = (const float4*)g_table;   // 32 float4 per vocab row

    // pipelines: index depth 6, xg depth 3
    int I3 = x[0 * BD + b];
    int I4 = x[1 * BD + b];
    int I5 = x[2 * BD + b];
    float4 XG0 = __ldg(tab4 + I3 * 32 + lane);   // t=0  (i,f,g,o)
    float4 XG1 = __ldg(tab4 + I4 * 32 + lane);   // t=1
    float4 XG2 = __ldg(tab4 + I5 * 32 + lane);   // t=2
    I3 = x[3 * BD + b];
    I4 = x[4 * BD + b];
    I5 = x[5 * BD + b];

    float c = 0.f;
    float* hs = g_hs + (size_t)b * TD * HID;

    for (int t = 0; t < TD; t++) {
        // prefetch xg for t+3 (2 bodies of slack), index for t+6
        float4 nxg = __ldg(tab4 + I3 * 32 + lane);
        int nI = 0;
        if (t + 6 < TD) nI = x[(t + 6) * BD + b];

        // load h (16 half2 = 4 x LDS.128, broadcast)
        const uint4* hq = (const uint4*)hbuf[warp][t & 1];
        uint4 q0 = hq[0], q1 = hq[1], q2 = hq[2], q3 = hq[3];
        __half2 h2[HID / 2];
        h2[0]  = u2h2(q0.x); h2[1]  = u2h2(q0.y); h2[2]  = u2h2(q0.z); h2[3]  = u2h2(q0.w);
        h2[4]  = u2h2(q1.x); h2[5]  = u2h2(q1.y); h2[6]  = u2h2(q1.z); h2[7]  = u2h2(q1.w);
        h2[8]  = u2h2(q2.x); h2[9]  = u2h2(q2.y); h2[10] = u2h2(q2.z); h2[11] = u2h2(q2.w);
        h2[12] = u2h2(q3.x); h2[13] = u2h2(q3.y); h2[14] = u2h2(q3.z); h2[15] = u2h2(q3.w);

        // 8 independent HFMA2 chains (2 per gate, depth 8)
        __half2 z = __float2half2_rn(0.f);
        __half2 aA[4] = {z, z, z, z};
        __half2 aB[4] = {z, z, z, z};
#pragma unroll
        for (int k = 0; k < 8; k++) {
#pragma unroll
            for (int g = 0; g < 4; g++) {
                aA[g] = __hfma2(W2[g][k],     h2[k],     aA[g]);
                aB[g] = __hfma2(W2[g][k + 8], h2[k + 8], aB[g]);
            }
        }
        // fold + fp32 combine with xg
        float2 fi = __half22float2(__hadd2(aA[0], aB[0]));
        float2 ff = __half22float2(__hadd2(aA[1], aB[1]));
        float2 fg = __half22float2(__hadd2(aA[2], aB[2]));
        float2 fo = __half22float2(__hadd2(aA[3], aB[3]));
        float ai = XG0.x + fi.x + fi.y;
        float af = XG0.y + ff.x + ff.y;
        float ag = XG0.z + fg.x + fg.y;
        float ao = XG0.w + fo.x + fo.y;

        // activations (branchless, packed): (i,f)=sigmoid ; (g,o)=(tanh,sigmoid)
        unsigned long long aif = pk(ai, af);
        unsigned long long ago = pk(ag, ao);
        unsigned long long sif = fma2(tanh2(mul2(aif, HALF2)), HALF2, HALF2);
        unsigned long long sgo = fma2(tanh2(mul2(ago, SC_GO)), SC_GO, BI_GO);

        float iv, fv, gv, ov;
        upk(sif, iv, fv);
        upk(sgo, gv, ov);

        c = fmaf(fv, c, iv * gv);          // c = f*c + i*g
        float h = ov * tanh_ap(c);         // h = o*tanh(c)

        ((__half*)hbuf[warp][(t + 1) & 1])[lane] = __float2half_rn(h);
        hs[t * HID + lane] = h;            // coalesced 128B per warp
        __syncwarp();

        XG0 = XG1; XG1 = XG2; XG2 = nxg;
        I3 = I4; I4 = I5; I5 = nI;
    }
}

// ---------------- K2: fused FF head + softmax over T ------------------------
__global__ __launch_bounds__(256, 1)
void head_softmax_kernel(const float* __restrict__ W1, const float* __restrict__ b1,
                         const float* __restrict__ W2, const float* __restrict__ b2,
                         float* __restrict__ out) {
    __shared__ unsigned long long W1p[FF * HID];
    __shared__ unsigned long long W2p[NCLS * FF];
    __shared__ float b1s[FF], b2s[NCLS];
    __shared__ float wredm[8][NCLS], wreds[8][NCLS];

    int tid = threadIdx.x;
    for (int i = tid; i < FF * HID; i += 256) { float w = W1[i]; W1p[i] = pk(w, w); }
    if (tid < NCLS * FF) { float w = W2[tid]; W2p[tid] = pk(w, w); }
    if (tid < FF)   b1s[tid] = b1[tid];
    if (tid < NCLS) b2s[tid] = b2[tid];
    __syncthreads();

    int b  = blockIdx.x;
    int t0 = tid * 2;
    const float* hr = g_hs + ((size_t)b * TD + t0) * HID;

    unsigned long long h2[HID];
#pragma unroll
    for (int k4 = 0; k4 < HID / 4; k4++) {
        float4 u = ((const float4*)hr)[k4];
        float4 v = ((const float4*)(hr + HID))[k4];
        h2[k4 * 4 + 0] = pk(u.x, v.x);
        h2[k4 * 4 + 1] = pk(u.y, v.y);
        h2[k4 * 4 + 2] = pk(u.z, v.z);
        h2[k4 * 4 + 3] = pk(u.w, v.w);
    }

    unsigned long long z2[FF];
#pragma unroll
    for (int f = 0; f < FF; f++) {
        unsigned long long acc = pk(b1s[f], b1s[f]);
#pragma unroll
        for (int k = 0; k < HID; k++) acc = fma2(W1p[f * HID + k], h2[k], acc);
        float lo, hi; upk(acc, lo, hi);
        z2[f] = pk(fmaxf(lo, 0.f), fmaxf(hi, 0.f));
    }

    float va[NCLS], vb[NCLS];
#pragma unroll
    for (int c = 0; c < NCLS; c++) {
        unsigned long long acc = pk(b2s[c], b2s[c]);
#pragma unroll
        for (int k = 0; k < FF; k++) acc = fma2(W2p[c * FF + k], z2[k], acc);
        upk(acc, va[c], vb[c]);
    }

    // --- softmax over T (across the whole CTA) ---
    int wid = tid >> 5, lid = tid & 31;
    float vm[NCLS];
#pragma unroll
    for (int c = 0; c < NCLS; c++) vm[c] = fmaxf(va[c], vb[c]);
#pragma unroll
    for (int off = 16; off; off >>= 1)
#pragma unroll
        for (int c = 0; c < NCLS; c++)
            vm[c] = fmaxf(vm[c], __shfl_xor_sync(0xffffffffu, vm[c], off));
    if (lid == 0)
#pragma unroll
        for (int c = 0; c < NCLS; c++) wredm[wid][c] = vm[c];
    __syncthreads();
    float gmax[NCLS];
#pragma unroll
    for (int c = 0; c < NCLS; c++) {
        float m = wredm[0][c];
#pragma unroll
        for (int w = 1; w < 8; w++) m = fmaxf(m, wredm[w][c]);
        gmax[c] = m;
    }
    float sm[NCLS];
#pragma unroll
    for (int c = 0; c < NCLS; c++) {
        va[c] = __expf(va[c] - gmax[c]);
        vb[c] = __expf(vb[c] - gmax[c]);
        sm[c] = va[c] + vb[c];
    }
#pragma unroll
    for (int off = 16; off; off >>= 1)
#pragma unroll
        for (int c = 0; c < NCLS; c++)
            sm[c] += __shfl_xor_sync(0xffffffffu, sm[c], off);
    if (lid == 0)
#pragma unroll
        for (int c = 0; c < NCLS; c++) wreds[wid][c] = sm[c];
    __syncthreads();
    float inv[NCLS];
#pragma unroll
    for (int c = 0; c < NCLS; c++) {
        float s = wreds[0][c];
#pragma unroll
        for (int w = 1; w < 8; w++) s += wreds[w][c];
        inv[c] = 1.0f / s;
    }

    float* o0 = out + (size_t)t0 * BD * NCLS + (size_t)b * NCLS;
#pragma unroll
    for (int c = 0; c < NCLS; c++) o0[c] = va[c] * inv[c];
#pragma unroll
    for (int c = 0; c < NCLS; c++) o0[BD * NCLS + c] = vb[c] * inv[c];
}

// ---------------- launch -----------------------------------------------------
extern "C" void kernel_launch(void* const* d_in, const int* in_sizes, int n_in,
                              void* d_out, int out_size) {
    (void)in_sizes; (void)n_in; (void)out_size;
    const int*   x    = (const int*)  d_in[0];
    const float* emb  = (const float*)d_in[1];
    const float* W_ih = (const float*)d_in[2];
    const float* W_hh = (const float*)d_in[3];
    const float* b_ih = (const float*)d_in[4];
    const float* b_hh = (const float*)d_in[5];
    const float* W1   = (const float*)d_in[6];
    const float* b1   = (const float*)d_in[7];
    const float* W2   = (const float*)d_in[8];
    const float* b2   = (const float*)d_in[9];

    table_kernel<<<VOCAB / 8, 256>>>(emb, W_ih, b_ih, b_hh);
    lstm_kernel<<<BD / 4, 128>>>(x, W_hh);
    head_softmax_kernel<<<BD, 256>>>(W1, b1, W2, b2, (float*)d_out);
}